// round 15
// baseline (speedup 1.0000x reference)
#include <cuda_runtime.h>
#include <cstdint>

// CostVolume: out[b, dy*9+dx, y, x] = leaky( mean_c( c1[b,c,y,x] * warped[b,c,y+dy-4,x+dx-4] ) )
// B=8, C=192, H=128, W=160, 81 offsets.
// Round 14: R13 with NON-VOLATILE computational asm (FMA2/PACK2/UNPACK2).
// asm volatile was a compiler scheduling fence that serialized LDS->FMA per
// channel; removing it enables cross-channel software pipelining.

#define SR 4
#define C_TOTAL 192
#define H_TOTAL 128
#define W_TOTAL 160
#define B_TOTAL 8

#define TW 32
#define TH 4
#define NUNIT 20
#define NTHREADS (NUNIT * 8)      // 160
#define CC 4
#define NCHUNK (C_TOTAL / CC)     // 48
#define HH 12                     // TH + 2*SR
#define WPAD 44

#define C1_WORDS (CC * TH * TW)                // 512
#define BUF_WORDS (C1_WORDS + CC * HH * WPAD)  // 512 + 2112 = 2624
#define BUF_BYTES (BUF_WORDS * 4)              // 10496

#define C1_SLOTS (CC * TH * 8)         // 128
#define W_SLOTS  (CC * HH * 10)        // 480
#define TOT_SLOTS (C1_SLOTS + W_SLOTS) // 608

// unit tables. warp = 4 consecutive units.
// w0: singles (pr=0). pairs: output A=(ya, s-ya), output B=(ya+1, s-ya-1).
__constant__ unsigned char u_s[NUNIT] = {0,9,2,11, 3,3,4,4, 5,5,6,6, 7,7,8,8, 1,2,9,10};
__constant__ unsigned char u_y[NUNIT] = {0,1,2,3,  0,2,0,2, 0,2,0,2, 0,2,0,2, 0,0,2,2};
__constant__ unsigned char u_p[NUNIT] = {0,0,0,0,  1,1,1,1, 1,1,1,1, 1,1,1,1, 1,1,1,1};

// NOTE: computational asm is NOT volatile — lets the compiler pipeline.
#define FMA2(d, a, b) \
    asm("fma.rn.f32x2 %0, %1, %2, %0;" : "+l"(d) : "l"(a), "l"(b))
#define PACK2(d, lo, hi) \
    asm("mov.b64 %0, {%1, %2};" : "=l"(d) : "f"(lo), "f"(hi))
#define UNPACK2(lo, hi, v) \
    asm("mov.b64 {%0, %1}, %2;" : "=f"(lo), "=f"(hi) : "l"(v))
#define CP16(smem_a, gptr, sz) \
    asm volatile("cp.async.cg.shared.global [%0], [%1], 16, %2;" \
                 :: "r"(smem_a), "l"(gptr), "r"(sz))
#define CP_COMMIT() asm volatile("cp.async.commit_group;")
#define CP_WAIT(n)  asm volatile("cp.async.wait_group %0;" :: "n"(n))

__device__ __forceinline__ uint32_t smem_u32(const void* p) {
    uint32_t a;
    asm("{ .reg .u64 t; cvta.to.shared.u64 t, %1; cvt.u32.u64 %0, t; }" : "=r"(a) : "l"(p));
    return a;
}

__global__ __launch_bounds__(NTHREADS, 3)
void costvol_kernel(const float* __restrict__ c1,
                    const float* __restrict__ warped,
                    const float* __restrict__ alpha,
                    float* __restrict__ out) {
    __shared__ __align__(16) float s_all[3][BUF_WORDS];   // 31.5 KB

    const int tid = threadIdx.x;
    const int xg  = tid & 7;            // x-group: 4 px each
    const int u   = tid >> 3;           // unit 0..19
    const int tx0 = xg * 4;
    const int x0  = blockIdx.x * TW;
    const int y0t = blockIdx.y * TH;
    const int b   = blockIdx.z;

    const int s   = u_s[u];             // shared window row
    const int ya  = u_y[u];             // first output pixel row
    const int pr  = u_p[u];             // pair flag (warp-uniform)
    const int yb  = (ya + 1 < TH) ? (ya + 1) : (TH - 1);
    const int dy1 = s - ya;
    const int dy2 = dy1 - 1;

    const size_t plane = (size_t)H_TOTAL * W_TOTAL;
    const float* c1b = c1     + (size_t)b * C_TOTAL * plane;
    const float* wb  = warped + (size_t)b * C_TOTAL * plane;
    const float  av  = alpha[0];
    const size_t CHSTEP = (size_t)CC * plane;

    const uint32_t sbase = smem_u32(&s_all[0][0]);

    // ---- staging descriptors: 4 slots/thread; dst byte-addr | active(bit0) ----
    const float* src[4];
    uint32_t     dstw[4];
    #pragma unroll
    for (int i = 0; i < 4; i++) {
        int j = tid + i * NTHREADS;
        if (j < C1_SLOTS) {
            int c   = j >> 5;               // 32 float4 slots per channel
            int rem = j & 31;
            int r   = rem >> 3;
            int sl  = rem & 7;
            src[i]  = c1b + (size_t)c * plane + (size_t)(y0t + r) * W_TOTAL + (x0 + sl * 4);
            dstw[i] = (uint32_t)(((c * TH + r) * TW + sl * 4) * 4) | 1u;
        } else if (j < TOT_SLOTS) {
            int h   = j - C1_SLOTS;
            int c   = h / (HH * 10);
            int rem = h - c * (HH * 10);
            int r   = rem / 10;
            int k   = rem - r * 10;
            int gy  = y0t + r - SR;
            int gx  = x0 - SR + 4 * k;
            bool ok = ((unsigned)gy < (unsigned)H_TOTAL) &&
                      ((unsigned)gx <= (unsigned)(W_TOTAL - 4));
            src[i]  = ok ? (wb + (size_t)c * plane + (size_t)gy * W_TOTAL + gx) : wb;
            dstw[i] = (uint32_t)((C1_WORDS + (c * HH + r) * WPAD + 4 * k) * 4) | (ok ? 1u : 0u);
        } else {
            // inactive: zero-size copy into never-read halo pad
            src[i]  = wb;
            dstw[i] = (uint32_t)((C1_WORDS + 40) * 4);
        }
    }

    // ---- accumulators ----
    unsigned long long Ae[5][2], Ac[5][2];   // output A: (ya, dy1)
    unsigned long long Be[5][2], Bc[5][2];   // output B: (yb, dy2), pairs only
    #pragma unroll
    for (int k = 0; k < 5; k++) {
        Ae[k][0] = 0ull; Ae[k][1] = 0ull; Ac[k][0] = 0ull; Ac[k][1] = 0ull;
        Be[k][0] = 0ull; Be[k][1] = 0ull; Bc[k][0] = 0ull; Bc[k][1] = 0ull;
    }

    // ---- prologue: chunk 0 -> ring buffer 0 ----
    #pragma unroll
    for (int i = 0; i < 4; i++) {
        CP16(sbase + (dstw[i] & ~15u), src[i], (int)(dstw[i] & 1u) * 16);
        src[i] += CHSTEP;
    }
    CP_COMMIT();

    uint32_t curoff = 0, nxtoff = BUF_BYTES;

    #pragma unroll 1
    for (int ch = 0; ch < NCHUNK; ch++) {
        if (ch + 1 < NCHUNK) {
            #pragma unroll
            for (int i = 0; i < 4; i++) {
                CP16(sbase + nxtoff + (dstw[i] & ~15u), src[i], (int)(dstw[i] & 1u) * 16);
                src[i] += CHSTEP;
            }
            CP_COMMIT();
            CP_WAIT(1);
        } else {
            CP_WAIT(0);
        }
        __syncthreads();   // single barrier per chunk (ring depth 3)

        const float* buf = (const float*)((const char*)&s_all[0][0] + curoff);
        #pragma unroll
        for (int c = 0; c < CC; c++) {
            const float* wrow = buf + C1_WORDS + (c * HH + s) * WPAD + tx0;
            const ulonglong2 wv0 = *(const ulonglong2*)(wrow);
            const ulonglong2 wv1 = *(const ulonglong2*)(wrow + 4);
            const ulonglong2 wv2 = *(const ulonglong2*)(wrow + 8);
            const unsigned long long P[6] = {wv0.x, wv0.y, wv1.x, wv1.y, wv2.x, wv2.y};

            const ulonglong2 a1v = *(const ulonglong2*)(buf + (c * TH + ya) * TW + tx0);

            float f0, f1, f2, f3;
            unsigned long long r1x, r1y;
            UNPACK2(f0, f1, a1v.x);  PACK2(r1x, f1, f0);
            UNPACK2(f2, f3, a1v.y);  PACK2(r1y, f3, f2);

            #pragma unroll
            for (int k = 0; k < 5; k++) {
                FMA2(Ae[k][0], a1v.x, P[k]);
                FMA2(Ae[k][1], a1v.y, P[k + 1]);
                FMA2(Ac[k][0], r1x,   P[k]);
                FMA2(Ac[k][1], r1y,   P[k + 1]);
            }

            if (pr) {   // warp-uniform: warp 0 skips the whole B side
                const ulonglong2 a2v = *(const ulonglong2*)(buf + (c * TH + yb) * TW + tx0);
                float g0, g1, g2, g3;
                unsigned long long r2x, r2y;
                UNPACK2(g0, g1, a2v.x);  PACK2(r2x, g1, g0);
                UNPACK2(g2, g3, a2v.y);  PACK2(r2y, g3, g2);
                #pragma unroll
                for (int k = 0; k < 5; k++) {
                    FMA2(Be[k][0], a2v.x, P[k]);
                    FMA2(Be[k][1], a2v.y, P[k + 1]);
                    FMA2(Bc[k][0], r2x,   P[k]);
                    FMA2(Bc[k][1], r2y,   P[k + 1]);
                }
            }
        }

        curoff = nxtoff;
        nxtoff += BUF_BYTES;
        if (nxtoff == 3 * BUF_BYTES) nxtoff = 0;
    }

    // ---- epilogue: route, mean, leaky-relu, ST.128 ----
    const float inv = 1.0f / (float)C_TOTAL;

    // output A: (row ya, dy1)
    {
        float e_lo[5][2], e_hi[5][2], c_lo[5][2], c_hi[5][2];
        #pragma unroll
        for (int k = 0; k < 5; k++) {
            UNPACK2(e_lo[k][0], e_hi[k][0], Ae[k][0]);
            UNPACK2(e_lo[k][1], e_hi[k][1], Ae[k][1]);
            UNPACK2(c_lo[k][0], c_hi[k][0], Ac[k][0]);
            UNPACK2(c_lo[k][1], c_hi[k][1], Ac[k][1]);
        }
        float* ob = out + (size_t)b * 81 * plane + (size_t)(dy1 * 9) * plane
                        + (size_t)(y0t + ya) * W_TOTAL + (x0 + tx0);
        #pragma unroll
        for (int dx = 0; dx < 9; dx++) {
            float r0, r1, r2, r3;
            if ((dx & 1) == 0) {
                int k = dx >> 1;
                r0 = e_lo[k][0]; r1 = e_hi[k][0]; r2 = e_lo[k][1]; r3 = e_hi[k][1];
            } else {
                int k = dx >> 1;
                r0 = c_hi[k][0]; r1 = c_lo[k + 1][0]; r2 = c_hi[k][1]; r3 = c_lo[k + 1][1];
            }
            r0 *= inv; r1 *= inv; r2 *= inv; r3 *= inv;
            float4 v;
            v.x = (r0 >= 0.f) ? r0 : av * r0;
            v.y = (r1 >= 0.f) ? r1 : av * r1;
            v.z = (r2 >= 0.f) ? r2 : av * r2;
            v.w = (r3 >= 0.f) ? r3 : av * r3;
            *(float4*)(ob + (size_t)dx * plane) = v;
        }
    }

    // output B: (row yb, dy2) — pairs only (warp-uniform)
    if (pr) {
        float e_lo[5][2], e_hi[5][2], c_lo[5][2], c_hi[5][2];
        #pragma unroll
        for (int k = 0; k < 5; k++) {
            UNPACK2(e_lo[k][0], e_hi[k][0], Be[k][0]);
            UNPACK2(e_lo[k][1], e_hi[k][1], Be[k][1]);
            UNPACK2(c_lo[k][0], c_hi[k][0], Bc[k][0]);
            UNPACK2(c_lo[k][1], c_hi[k][1], Bc[k][1]);
        }
        float* ob = out + (size_t)b * 81 * plane + (size_t)(dy2 * 9) * plane
                        + (size_t)(y0t + yb) * W_TOTAL + (x0 + tx0);
        #pragma unroll
        for (int dx = 0; dx < 9; dx++) {
            float r0, r1, r2, r3;
            if ((dx & 1) == 0) {
                int k = dx >> 1;
                r0 = e_lo[k][0]; r1 = e_hi[k][0]; r2 = e_lo[k][1]; r3 = e_hi[k][1];
            } else {
                int k = dx >> 1;
                r0 = c_hi[k][0]; r1 = c_lo[k + 1][0]; r2 = c_hi[k][1]; r3 = c_lo[k + 1][1];
            }
            r0 *= inv; r1 *= inv; r2 *= inv; r3 *= inv;
            float4 v;
            v.x = (r0 >= 0.f) ? r0 : av * r0;
            v.y = (r1 >= 0.f) ? r1 : av * r1;
            v.z = (r2 >= 0.f) ? r2 : av * r2;
            v.w = (r3 >= 0.f) ? r3 : av * r3;
            *(float4*)(ob + (size_t)dx * plane) = v;
        }
    }
}

extern "C" void kernel_launch(void* const* d_in, const int* in_sizes, int n_in,
                              void* d_out, int out_size) {
    const float* c1     = (const float*)d_in[0];
    const float* warped = (const float*)d_in[1];
    const float* alpha  = (const float*)d_in[2];
    float* out          = (float*)d_out;

    cudaFuncSetAttribute(costvol_kernel,
                         cudaFuncAttributePreferredSharedMemoryCarveout, 100);

    dim3 grid(W_TOTAL / TW, H_TOTAL / TH, B_TOTAL);   // (5, 32, 8) = 1280
    dim3 block(NTHREADS);                              // 160
    costvol_kernel<<<grid, block>>>(c1, warped, alpha, out);
}